// round 9
// baseline (speedup 1.0000x reference)
#include <cuda_runtime.h>

// ---- block layout ----
// [0,567)    kz5 main : 64 img x 126 colpairs x 18 chunks(R=14) = 145152 thr (exact)
// [567,709)  kz3 main : 64 img x 63 colpairs x 9 chunks(R=14)   = 36288 thr
// [709,773)  f^2 pass kz5 : 16384 rows (64 img x 256), 1 row/thread
// [773,805)  f^2 pass kz3 : 8192 rows  (64 img x 128), 1 row/thread
#define B5M        567
#define T3_THREADS 36288
#define B3M        142
#define B5F        64
#define B3F        32
#define NBLOCKS    (B5M + B3M + B5F + B3F)   // 805

__device__ double g_part[NBLOCKS];
__device__ int    g_count;

typedef unsigned long long u64;

__device__ __forceinline__ u64 pack2(float lo, float hi) {
    u64 r; asm("mov.b64 %0, {%1,%2};" : "=l"(r) : "f"(lo), "f"(hi)); return r;
}
__device__ __forceinline__ u64 fma2(u64 a, u64 b, u64 c) {
    u64 d; asm("fma.rn.f32x2 %0, %1, %2, %3;" : "=l"(d) : "l"(a), "l"(b), "l"(c)); return d;
}
__device__ __forceinline__ u64 add2(u64 a, u64 b) {
    u64 d; asm("add.rn.f32x2 %0, %1, %2;" : "=l"(d) : "l"(a), "l"(b)); return d;
}
__device__ __forceinline__ u64 mul2(u64 a, u64 b) {
    u64 d; asm("mul.rn.f32x2 %0, %1, %2;" : "=l"(d) : "l"(a), "l"(b)); return d;
}
__device__ __forceinline__ void unpack2(u64 v, float& lo, float& hi) {
    asm("mov.b64 {%0,%1}, %2;" : "=f"(lo), "=f"(hi) : "l"(v));
}
__device__ __forceinline__ float lo2(u64 v){ float a,b; unpack2(v,a,b); return a; }
__device__ __forceinline__ float hi2(u64 v){ float a,b; unpack2(v,a,b); return b; }

// ---- kz5 horizontal S0/Sc only (no S2) ----
__device__ __forceinline__ void hstats5(const float* __restrict__ p,
                                        u64 two2, u64 neg12, u64& o0, u64& oc)
{
    u64 A = *reinterpret_cast<const u64*>(p);      // (f0,f1)
    u64 B = *reinterpret_cast<const u64*>(p + 2);  // (f2,f3)
    u64 C = *reinterpret_cast<const u64*>(p + 4);  // (f4,f5)
    u64 pk1 = pack2(hi2(A), lo2(B));               // (f1,f2)
    u64 pk3 = pack2(hi2(B), lo2(C));               // (f3,f4)
    u64 s0 = add2(add2(A, pk1), add2(B, pk3));
    o0 = add2(s0, C);
    u64 d1 = fma2(neg12, pk1, pk3);                // f3-f1 | f4-f2
    u64 d2 = fma2(neg12, A, C);                    // f4-f0 | f5-f1
    oc = fma2(two2, d2, d1);
}

// ---- kz3 horizontal S0/Sc only ----
__device__ __forceinline__ void hstats3(const float* __restrict__ p,
                                        u64 neg12, u64& o0, u64& oc)
{
    u64 A = *reinterpret_cast<const u64*>(p);      // (f0,f1)
    u64 B = *reinterpret_cast<const u64*>(p + 2);  // (f2,f3)
    u64 pk1 = pack2(hi2(A), lo2(B));               // (f1,f2)
    o0 = add2(add2(A, pk1), B);
    oc = fma2(neg12, A, B);                        // f2-f0 | f3-f1
}

// ---- kz5 main: 2 cols x 14 rows, ring of (S0,Sc) row stats ----
__device__ __forceinline__ float work5(const float* __restrict__ f1, int t)
{
    const int img   = t / 2268;          // 126*18
    int rem         = t - img * 2268;
    const int chunk = rem / 126;
    const int cg    = rem - chunk * 126;
    const float* __restrict__ p = f1 + (size_t)img * 65536
                                + (size_t)(chunk * 14) * 256 + cg * 2;

    const u64 two2  = pack2(2.f, 2.f);
    const u64 neg12 = pack2(-1.f, -1.f);

    u64 r0[5], rc[5];
#pragma unroll
    for (int w = 0; w < 4; w++) { hstats5(p, two2, neg12, r0[w], rc[w]); p += 256; }

    u64 accA = 0ull, accB = 0ull;        // Sum S0^2 ; Sum (Sr^2 + Sc^2)
#pragma unroll
    for (int i = 0; i < 14; i++) {
        const int sl = (i + 4) % 5;
        hstats5(p, two2, neg12, r0[sl], rc[sl]);
        p += 256;
        const int a0 = i % 5, a1 = (i+1) % 5, a2 = (i+2) % 5, a3 = (i+3) % 5;
        u64 S0 = add2(add2(r0[a0], r0[a1]), add2(r0[a2], r0[a3]));
        S0 = add2(S0, r0[sl]);
        u64 Sc = add2(add2(rc[a0], rc[a1]), add2(rc[a2], rc[a3]));
        Sc = add2(Sc, rc[sl]);
        u64 d1 = fma2(neg12, r0[a1], r0[a3]);
        u64 d2 = fma2(neg12, r0[a0], r0[sl]);
        u64 Sr = fma2(two2, d2, d1);
        accA = fma2(S0, S0, accA);
        accB = fma2(Sr, Sr, accB);
        accB = fma2(Sc, Sc, accB);
    }
    float aL, aH, bL, bH;
    unpack2(accA, aL, aH); unpack2(accB, bL, bH);
    return (1.f/25.f) * (aL + aH) + (12.f/(25.f*24.f)) * (bL + bH);
}

// ---- kz3 main: 2 cols x 14 rows ----
__device__ __forceinline__ float work3(const float* __restrict__ f0, int t)
{
    const int img   = t / 567;           // 63*9
    int rem         = t - img * 567;
    const int chunk = rem / 63;
    const int cg    = rem - chunk * 63;
    const float* __restrict__ p = f0 + (size_t)img * 16384
                                + (size_t)(chunk * 14) * 128 + cg * 2;

    const u64 neg12 = pack2(-1.f, -1.f);

    u64 r0[3], rc[3];
#pragma unroll
    for (int w = 0; w < 2; w++) { hstats3(p, neg12, r0[w], rc[w]); p += 128; }

    u64 accA = 0ull, accB = 0ull;
#pragma unroll
    for (int i = 0; i < 14; i++) {
        const int sl = (i + 2) % 3;
        hstats3(p, neg12, r0[sl], rc[sl]);
        p += 128;
        const int a0 = i % 3, a1 = (i + 1) % 3;
        u64 S0 = add2(add2(r0[a0], r0[a1]), r0[sl]);
        u64 Sc = add2(add2(rc[a0], rc[a1]), rc[sl]);
        u64 Sr = fma2(neg12, r0[a0], r0[sl]);
        accA = fma2(S0, S0, accA);
        accB = fma2(Sr, Sr, accB);
        accB = fma2(Sc, Sc, accB);
    }
    float aL, aH, bL, bH;
    unpack2(accA, aL, aH); unpack2(accB, bL, bH);
    return (1.f/9.f) * (aL + aH) + (12.f/(9.f*8.f)) * (bL + bH);
}

// ---- weighted f^2 row pass, kz5 (W=256): wx ramp 1..4 | 5 | 4..1 ----
__device__ __forceinline__ float frow5(const float* __restrict__ f1, int t)
{
    const int img = t >> 8;
    const int row = t & 255;
    const float* __restrict__ p = f1 + (size_t)img * 65536 + (size_t)row * 256;
    const u64* __restrict__ q = reinterpret_cast<const u64*>(p);

    u64 acci = 0ull;                     // interior, weight 5
#pragma unroll 4
    for (int i = 2; i < 126; i++) {
        u64 F = q[i];
        acci = fma2(F, F, acci);
    }
    u64 acce = 0ull;                     // edges, explicit weights
    {
        u64 F, T;
        F = q[0];   T = mul2(F, pack2(1.f, 2.f)); acce = fma2(F, T, acce);
        F = q[1];   T = mul2(F, pack2(3.f, 4.f)); acce = fma2(F, T, acce);
        F = q[126]; T = mul2(F, pack2(4.f, 3.f)); acce = fma2(F, T, acce);
        F = q[127]; T = mul2(F, pack2(2.f, 1.f)); acce = fma2(F, T, acce);
    }
    float iL, iH, eL, eH;
    unpack2(acci, iL, iH); unpack2(acce, eL, eH);
    int wy = min(min(row + 1, 256 - row), 5);
    return (float)wy * (5.f * (iL + iH) + (eL + eH));
}

// ---- weighted f^2 row pass, kz3 (W=128): wx ramp 1,2 | 3 | 2,1 ----
__device__ __forceinline__ float frow3(const float* __restrict__ f0, int t)
{
    const int img = t >> 7;
    const int row = t & 127;
    const float* __restrict__ p = f0 + (size_t)img * 16384 + (size_t)row * 128;
    const u64* __restrict__ q = reinterpret_cast<const u64*>(p);

    u64 acci = 0ull;                     // interior, weight 3
#pragma unroll 4
    for (int i = 1; i < 63; i++) {
        u64 F = q[i];
        acci = fma2(F, F, acci);
    }
    u64 acce = 0ull;
    {
        u64 F, T;
        F = q[0];  T = mul2(F, pack2(1.f, 2.f)); acce = fma2(F, T, acce);
        F = q[63]; T = mul2(F, pack2(2.f, 1.f)); acce = fma2(F, T, acce);
    }
    float iL, iH, eL, eH;
    unpack2(acci, iL, iH); unpack2(acce, eL, eH);
    int wy = min(min(row + 1, 128 - row), 3);
    return (float)wy * (3.f * (iL + iH) + (eL + eH));
}

__global__ void __launch_bounds__(256, 4) fused_kernel(const float* __restrict__ f0,
                                                       const float* __restrict__ f1,
                                                       float* __restrict__ out)
{
    const int tid = threadIdx.x;
    const int b   = blockIdx.x;
    float acc = 0.f;
    double scale;

    const double sc5 = 1.0 / (32.0 * 252.0 * 252.0);
    const double sc3 = 1.0 / (32.0 * 126.0 * 126.0);

    if (b < B5M) {                                   // kz5 main (negative)
        acc = work5(f1, b * 256 + tid);
        scale = -sc5;
    } else if (b < B5M + B3M) {                      // kz3 main (negative)
        const int t = (b - B5M) * 256 + tid;
        if (t < T3_THREADS) acc = work3(f0, t);
        scale = -sc3;
    } else if (b < B5M + B3M + B5F) {                // f^2 kz5 (positive)
        acc = frow5(f1, (b - B5M - B3M) * 256 + tid);
        scale = sc5;
    } else {                                         // f^2 kz3 (positive)
        acc = frow3(f0, (b - B5M - B3M - B5F) * 256 + tid);
        scale = sc3;
    }

#pragma unroll
    for (int o = 16; o > 0; o >>= 1) acc += __shfl_down_sync(0xffffffffu, acc, o);
    __shared__ float wsum[8];
    __shared__ bool  lastflag;
    if ((tid & 31) == 0) wsum[tid >> 5] = acc;
    __syncthreads();
    if (tid < 32) {
        float v = (tid < 8) ? wsum[tid] : 0.f;
#pragma unroll
        for (int o = 4; o > 0; o >>= 1) v += __shfl_down_sync(0xffffffffu, v, o);
        if (tid == 0) {
            g_part[b] = (double)v * scale;
            __threadfence();
            int done = atomicAdd(&g_count, 1);
            lastflag = (done == NBLOCKS - 1);
        }
    }
    __syncthreads();

    if (lastflag) {
        __threadfence();
        double s = 0.0;
        for (int i = tid; i < NBLOCKS; i += 256) s += g_part[i];
#pragma unroll
        for (int o = 16; o > 0; o >>= 1) s += __shfl_down_sync(0xffffffffu, s, o);
        __shared__ double ws[8];
        if ((tid & 31) == 0) ws[tid >> 5] = s;
        __syncthreads();
        if (tid < 32) {
            double v = (tid < 8) ? ws[tid] : 0.0;
#pragma unroll
            for (int o = 4; o > 0; o >>= 1) v += __shfl_down_sync(0xffffffffu, v, o);
            if (tid == 0) { out[0] = (float)v; g_count = 0; }
        }
    }
}

extern "C" void kernel_launch(void* const* d_in, const int* in_sizes, int n_in,
                              void* d_out, int out_size)
{
    const float* flow0 = (const float*)d_in[0];  // (32,2,128,128)
    const float* flow1 = (const float*)d_in[1];  // (32,2,256,256)
    if (n_in >= 2 && in_sizes[0] > in_sizes[1]) {
        const float* t = flow0; flow0 = flow1; flow1 = t;
    }
    fused_kernel<<<NBLOCKS, 256>>>(flow0, flow1, (float*)d_out);
}

// round 10
// speedup vs baseline: 3.2966x; 3.2966x over previous
#include <cuda_runtime.h>

// ---- block layout (f^2 first: memory-bound, prefetches L2, overlaps compute) ----
// [0,64)     f^2 kz5 : 1 block per image (64 img of 256x256)
// [64,96)    f^2 kz3 : 1 block per image (64 img of 128x128), 2 img/block -> 32 blocks
// [96,663)   kz5 main: 64 img x 126 colpairs x 18 chunks(R=14) = 145152 thr = 567 blocks
// [663,805)  kz3 main: 64 img x 63 colpairs x 9 chunks(R=14)   = 36288 thr  = 142 blocks
#define B5F        64
#define B3F        32
#define B5M        567
#define T3_THREADS 36288
#define B3M        142
#define NBLOCKS    (B5F + B3F + B5M + B3M)   // 805

__device__ double g_part[NBLOCKS];
__device__ int    g_count;

typedef unsigned long long u64;

__device__ __forceinline__ u64 pack2(float lo, float hi) {
    u64 r; asm("mov.b64 %0, {%1,%2};" : "=l"(r) : "f"(lo), "f"(hi)); return r;
}
__device__ __forceinline__ u64 fma2(u64 a, u64 b, u64 c) {
    u64 d; asm("fma.rn.f32x2 %0, %1, %2, %3;" : "=l"(d) : "l"(a), "l"(b), "l"(c)); return d;
}
__device__ __forceinline__ u64 add2(u64 a, u64 b) {
    u64 d; asm("add.rn.f32x2 %0, %1, %2;" : "=l"(d) : "l"(a), "l"(b)); return d;
}
__device__ __forceinline__ u64 mul2(u64 a, u64 b) {
    u64 d; asm("mul.rn.f32x2 %0, %1, %2;" : "=l"(d) : "l"(a), "l"(b)); return d;
}
__device__ __forceinline__ void unpack2(u64 v, float& lo, float& hi) {
    asm("mov.b64 {%0,%1}, %2;" : "=f"(lo), "=f"(hi) : "l"(v));
}
__device__ __forceinline__ float lo2(u64 v){ float a,b; unpack2(v,a,b); return a; }
__device__ __forceinline__ float hi2(u64 v){ float a,b; unpack2(v,a,b); return b; }

// ---- kz5 horizontal S0/Sc only ----
__device__ __forceinline__ void hstats5(const float* __restrict__ p,
                                        u64 two2, u64 neg12, u64& o0, u64& oc)
{
    u64 A = *reinterpret_cast<const u64*>(p);      // (f0,f1)
    u64 B = *reinterpret_cast<const u64*>(p + 2);  // (f2,f3)
    u64 C = *reinterpret_cast<const u64*>(p + 4);  // (f4,f5)
    u64 pk1 = pack2(hi2(A), lo2(B));               // (f1,f2)
    u64 pk3 = pack2(hi2(B), lo2(C));               // (f3,f4)
    u64 s0 = add2(add2(A, pk1), add2(B, pk3));
    o0 = add2(s0, C);
    u64 d1 = fma2(neg12, pk1, pk3);
    u64 d2 = fma2(neg12, A, C);
    oc = fma2(two2, d2, d1);
}

// ---- kz3 horizontal S0/Sc only ----
__device__ __forceinline__ void hstats3(const float* __restrict__ p,
                                        u64 neg12, u64& o0, u64& oc)
{
    u64 A = *reinterpret_cast<const u64*>(p);      // (f0,f1)
    u64 B = *reinterpret_cast<const u64*>(p + 2);  // (f2,f3)
    u64 pk1 = pack2(hi2(A), lo2(B));               // (f1,f2)
    o0 = add2(add2(A, pk1), B);
    oc = fma2(neg12, A, B);
}

// ---- kz5 main: 2 cols x 14 rows ----
__device__ __forceinline__ float work5(const float* __restrict__ f1, int t)
{
    const int img   = t / 2268;          // 126*18
    int rem         = t - img * 2268;
    const int chunk = rem / 126;
    const int cg    = rem - chunk * 126;
    const float* __restrict__ p = f1 + (size_t)img * 65536
                                + (size_t)(chunk * 14) * 256 + cg * 2;

    const u64 two2  = pack2(2.f, 2.f);
    const u64 neg12 = pack2(-1.f, -1.f);

    u64 r0[5], rc[5];
#pragma unroll
    for (int w = 0; w < 4; w++) { hstats5(p, two2, neg12, r0[w], rc[w]); p += 256; }

    u64 accA = 0ull, accB = 0ull;
#pragma unroll
    for (int i = 0; i < 14; i++) {
        const int sl = (i + 4) % 5;
        hstats5(p, two2, neg12, r0[sl], rc[sl]);
        p += 256;
        const int a0 = i % 5, a1 = (i+1) % 5, a2 = (i+2) % 5, a3 = (i+3) % 5;
        u64 S0 = add2(add2(r0[a0], r0[a1]), add2(r0[a2], r0[a3]));
        S0 = add2(S0, r0[sl]);
        u64 Sc = add2(add2(rc[a0], rc[a1]), add2(rc[a2], rc[a3]));
        Sc = add2(Sc, rc[sl]);
        u64 d1 = fma2(neg12, r0[a1], r0[a3]);
        u64 d2 = fma2(neg12, r0[a0], r0[sl]);
        u64 Sr = fma2(two2, d2, d1);
        accA = fma2(S0, S0, accA);
        accB = fma2(Sr, Sr, accB);
        accB = fma2(Sc, Sc, accB);
    }
    float aL, aH, bL, bH;
    unpack2(accA, aL, aH); unpack2(accB, bL, bH);
    return (1.f/25.f) * (aL + aH) + (12.f/(25.f*24.f)) * (bL + bH);
}

// ---- kz3 main: 2 cols x 14 rows ----
__device__ __forceinline__ float work3(const float* __restrict__ f0, int t)
{
    const int img   = t / 567;           // 63*9
    int rem         = t - img * 567;
    const int chunk = rem / 63;
    const int cg    = rem - chunk * 63;
    const float* __restrict__ p = f0 + (size_t)img * 16384
                                + (size_t)(chunk * 14) * 128 + cg * 2;

    const u64 neg12 = pack2(-1.f, -1.f);

    u64 r0[3], rc[3];
#pragma unroll
    for (int w = 0; w < 2; w++) { hstats3(p, neg12, r0[w], rc[w]); p += 128; }

    u64 accA = 0ull, accB = 0ull;
#pragma unroll
    for (int i = 0; i < 14; i++) {
        const int sl = (i + 2) % 3;
        hstats3(p, neg12, r0[sl], rc[sl]);
        p += 128;
        const int a0 = i % 3, a1 = (i + 1) % 3;
        u64 S0 = add2(add2(r0[a0], r0[a1]), r0[sl]);
        u64 Sc = add2(add2(rc[a0], rc[a1]), rc[sl]);
        u64 Sr = fma2(neg12, r0[a0], r0[sl]);
        accA = fma2(S0, S0, accA);
        accB = fma2(Sr, Sr, accB);
        accB = fma2(Sc, Sc, accB);
    }
    float aL, aH, bL, bH;
    unpack2(accA, aL, aH); unpack2(accB, bL, bH);
    return (1.f/9.f) * (aL + aH) + (12.f/(9.f*8.f)) * (bL + bH);
}

// ---- f^2 weighted pass, kz5: 1 block per 256x256 image ----
// u64 index idx = tid + 256*k ; colpair = idx & 127 == tid & 127 (constant/thread)
// rows = (tid>>7) + 2k ; wy != 5 exactly at k in {0,1,126,127}
__device__ __forceinline__ float frow5(const float* __restrict__ f1, int img, int tid)
{
    const u64* __restrict__ q = reinterpret_cast<const u64*>(f1 + (size_t)img * 65536);
    const int x0 = 2 * (tid & 127);
    const float wx0 = (float)min(min(x0 + 1, 256 - x0), 5);
    const float wx1 = (float)min(min(x0 + 2, 255 - x0), 5);
    const u64 wx2 = pack2(wx0, wx1);

    u64 acc5 = 0ull;                         // interior rows: weight 5*wx
#pragma unroll 8
    for (int k = 2; k < 126; k++) {
        u64 F = q[tid + (k << 8)];
        acc5 = fma2(F, mul2(F, wx2), acc5);
    }
    u64 acce = 0ull;                         // 8 edge rows: full wy*wx
    const int r0 = tid >> 7;
#pragma unroll
    for (int e = 0; e < 4; e++) {
        const int k = (e < 2) ? e : (124 + e);
        const int row = r0 + 2 * k;
        const float wy = (float)min(min(row + 1, 256 - row), 5);
        u64 F = q[tid + (k << 8)];
        acce = fma2(F, mul2(F, mul2(wx2, pack2(wy, wy))), acce);
    }
    float aL, aH, eL, eH;
    unpack2(acc5, aL, aH); unpack2(acce, eL, eH);
    return 5.f * (aL + aH) + (eL + eH);
}

// ---- f^2 weighted pass, kz3: 1 block per 2 images (128x128) ----
// per image: 8192 u64 ; idx = tid + 256*k, k=0..31 ; colpair = tid & 63 ;
// rows = (tid>>6) + 4k ; wy != 3 exactly at k in {0,31}
__device__ __forceinline__ float frow3img(const float* __restrict__ f0, int img, int tid)
{
    const u64* __restrict__ q = reinterpret_cast<const u64*>(f0 + (size_t)img * 16384);
    const int x0 = 2 * (tid & 63);
    const float wx0 = (float)min(min(x0 + 1, 128 - x0), 3);
    const float wx1 = (float)min(min(x0 + 2, 127 - x0), 3);
    const u64 wx2 = pack2(wx0, wx1);

    u64 acc3 = 0ull;
#pragma unroll 8
    for (int k = 1; k < 31; k++) {
        u64 F = q[tid + (k << 8)];
        acc3 = fma2(F, mul2(F, wx2), acc3);
    }
    u64 acce = 0ull;
    const int r0 = tid >> 6;
#pragma unroll
    for (int e = 0; e < 2; e++) {
        const int k = e * 31;
        const int row = r0 + 4 * k;
        const float wy = (float)min(min(row + 1, 128 - row), 3);
        u64 F = q[tid + (k << 8)];
        acce = fma2(F, mul2(F, mul2(wx2, pack2(wy, wy))), acce);
    }
    float aL, aH, eL, eH;
    unpack2(acc3, aL, aH); unpack2(acce, eL, eH);
    return 3.f * (aL + aH) + (eL + eH);
}

__global__ void __launch_bounds__(256, 4) fused_kernel(const float* __restrict__ f0,
                                                       const float* __restrict__ f1,
                                                       float* __restrict__ out)
{
    const int tid = threadIdx.x;
    const int b   = blockIdx.x;
    float acc = 0.f;
    double scale;

    const double sc5 = 1.0 / (32.0 * 252.0 * 252.0);
    const double sc3 = 1.0 / (32.0 * 126.0 * 126.0);

    if (b < B5F) {                                     // f^2 kz5 (positive)
        acc = frow5(f1, b, tid);
        scale = sc5;
    } else if (b < B5F + B3F) {                        // f^2 kz3 (positive), 2 imgs
        const int i0 = (b - B5F) * 2;
        acc = frow3img(f0, i0, tid) + frow3img(f0, i0 + 1, tid);
        scale = sc3;
    } else if (b < B5F + B3F + B5M) {                  // kz5 main (negative)
        acc = work5(f1, (b - B5F - B3F) * 256 + tid);
        scale = -sc5;
    } else {                                           // kz3 main (negative)
        const int t = (b - B5F - B3F - B5M) * 256 + tid;
        if (t < T3_THREADS) acc = work3(f0, t);
        scale = -sc3;
    }

#pragma unroll
    for (int o = 16; o > 0; o >>= 1) acc += __shfl_down_sync(0xffffffffu, acc, o);
    __shared__ float wsum[8];
    __shared__ bool  lastflag;
    if ((tid & 31) == 0) wsum[tid >> 5] = acc;
    __syncthreads();
    if (tid < 32) {
        float v = (tid < 8) ? wsum[tid] : 0.f;
#pragma unroll
        for (int o = 4; o > 0; o >>= 1) v += __shfl_down_sync(0xffffffffu, v, o);
        if (tid == 0) {
            g_part[b] = (double)v * scale;
            __threadfence();
            int done = atomicAdd(&g_count, 1);
            lastflag = (done == NBLOCKS - 1);
        }
    }
    __syncthreads();

    if (lastflag) {
        __threadfence();
        double s = 0.0;
        for (int i = tid; i < NBLOCKS; i += 256) s += g_part[i];
#pragma unroll
        for (int o = 16; o > 0; o >>= 1) s += __shfl_down_sync(0xffffffffu, s, o);
        __shared__ double ws[8];
        if ((tid & 31) == 0) ws[tid >> 5] = s;
        __syncthreads();
        if (tid < 32) {
            double v = (tid < 8) ? ws[tid] : 0.0;
#pragma unroll
            for (int o = 4; o > 0; o >>= 1) v += __shfl_down_sync(0xffffffffu, v, o);
            if (tid == 0) { out[0] = (float)v; g_count = 0; }
        }
    }
}

extern "C" void kernel_launch(void* const* d_in, const int* in_sizes, int n_in,
                              void* d_out, int out_size)
{
    const float* flow0 = (const float*)d_in[0];  // (32,2,128,128)
    const float* flow1 = (const float*)d_in[1];  // (32,2,256,256)
    if (n_in >= 2 && in_sizes[0] > in_sizes[1]) {
        const float* t = flow0; flow0 = flow1; flow1 = t;
    }
    fused_kernel<<<NBLOCKS, 256>>>(flow0, flow1, (float*)d_out);
}

// round 11
// speedup vs baseline: 3.3625x; 1.0200x over previous
#include <cuda_runtime.h>

// ---- block layout (f^2 first: memory-bound, warms L2, overlaps compute) ----
// [0,64)     f^2 kz5 : 1 block per image (64 img of 256x256)
// [64,96)    f^2 kz3 : 1 block per 2 images (64 img of 128x128)
// [96,663)   kz5 main: 64 img x 126 colpairs x 18 chunks(R=14) = 145152 thr = 567 blocks
// [663,805)  kz3 main: 64 img x 63 colpairs x 9 chunks(R=14)   = 36288 thr  = 142 blocks
#define B5F        64
#define B3F        32
#define B5M        567
#define T3_THREADS 36288
#define B3M        142
#define NBLOCKS    (B5F + B3F + B5M + B3M)   // 805

__device__ double g_part[NBLOCKS];
__device__ int    g_count;

typedef unsigned long long u64;

__device__ __forceinline__ u64 pack2(float lo, float hi) {
    u64 r; asm("mov.b64 %0, {%1,%2};" : "=l"(r) : "f"(lo), "f"(hi)); return r;
}
__device__ __forceinline__ u64 fma2(u64 a, u64 b, u64 c) {
    u64 d; asm("fma.rn.f32x2 %0, %1, %2, %3;" : "=l"(d) : "l"(a), "l"(b), "l"(c)); return d;
}
__device__ __forceinline__ u64 add2(u64 a, u64 b) {
    u64 d; asm("add.rn.f32x2 %0, %1, %2;" : "=l"(d) : "l"(a), "l"(b)); return d;
}
__device__ __forceinline__ u64 mul2(u64 a, u64 b) {
    u64 d; asm("mul.rn.f32x2 %0, %1, %2;" : "=l"(d) : "l"(a), "l"(b)); return d;
}
__device__ __forceinline__ void unpack2(u64 v, float& lo, float& hi) {
    asm("mov.b64 {%0,%1}, %2;" : "=f"(lo), "=f"(hi) : "l"(v));
}
__device__ __forceinline__ float lo2(u64 v){ float a,b; unpack2(v,a,b); return a; }
__device__ __forceinline__ float hi2(u64 v){ float a,b; unpack2(v,a,b); return b; }

// ---- hstats from pre-loaded raw registers ----
__device__ __forceinline__ void hstats5r(u64 A, u64 B, u64 C,
                                         u64 two2, u64 neg12, u64& o0, u64& oc)
{
    u64 pk1 = pack2(hi2(A), lo2(B));               // (f1,f2)
    u64 pk3 = pack2(hi2(B), lo2(C));               // (f3,f4)
    u64 s0 = add2(add2(A, pk1), add2(B, pk3));
    o0 = add2(s0, C);
    u64 d1 = fma2(neg12, pk1, pk3);
    u64 d2 = fma2(neg12, A, C);
    oc = fma2(two2, d2, d1);
}
__device__ __forceinline__ void hstats3r(u64 A, u64 B,
                                         u64 neg12, u64& o0, u64& oc)
{
    u64 pk1 = pack2(hi2(A), lo2(B));
    o0 = add2(add2(A, pk1), B);
    oc = fma2(neg12, A, B);
}

// ---- kz5 main: 2 cols x 14 rows, software-pipelined loads + incremental S0/Sc ----
__device__ __forceinline__ float work5(const float* __restrict__ f1, int t)
{
    const int img   = t / 2268;          // 126*18
    int rem         = t - img * 2268;
    const int chunk = rem / 126;
    const int cg    = rem - chunk * 126;
    const float* __restrict__ p = f1 + (size_t)img * 65536
                                + (size_t)(chunk * 14) * 256 + cg * 2;

    const u64 two2  = pack2(2.f, 2.f);
    const u64 neg12 = pack2(-1.f, -1.f);

    u64 r0[5], rc[5];
#pragma unroll
    for (int w = 0; w < 4; w++) {
        u64 A = *reinterpret_cast<const u64*>(p);
        u64 B = *reinterpret_cast<const u64*>(p + 2);
        u64 C = *reinterpret_cast<const u64*>(p + 4);
        hstats5r(A, B, C, two2, neg12, r0[w], rc[w]);
        p += 256;
    }
    // carry-in: sum of rows 0..3
    u64 S0p = add2(add2(r0[0], r0[1]), add2(r0[2], r0[3]));
    u64 Scp = add2(add2(rc[0], rc[1]), add2(rc[2], rc[3]));

    // prefetch row 4
    u64 A = *reinterpret_cast<const u64*>(p);
    u64 B = *reinterpret_cast<const u64*>(p + 2);
    u64 C = *reinterpret_cast<const u64*>(p + 4);
    p += 256;

    u64 accA = 0ull, accB = 0ull;
#pragma unroll
    for (int i = 0; i < 14; i++) {
        u64 nA, nB, nC;
        if (i < 13) {                     // prefetch row i+5
            nA = *reinterpret_cast<const u64*>(p);
            nB = *reinterpret_cast<const u64*>(p + 2);
            nC = *reinterpret_cast<const u64*>(p + 4);
            p += 256;
        }
        const int sl = (i + 4) % 5;
        hstats5r(A, B, C, two2, neg12, r0[sl], rc[sl]);

        u64 S0 = add2(S0p, r0[sl]);
        u64 Sc = add2(Scp, rc[sl]);
        const int a0 = i % 5, a1 = (i + 1) % 5, a3 = (i + 3) % 5;
        u64 d1 = fma2(neg12, r0[a1], r0[a3]);
        u64 d2 = fma2(neg12, r0[a0], r0[sl]);
        u64 Sr = fma2(two2, d2, d1);
        accA = fma2(S0, S0, accA);
        accB = fma2(Sr, Sr, accB);
        accB = fma2(Sc, Sc, accB);
        S0p = fma2(neg12, r0[a0], S0);    // drop leaving row
        Scp = fma2(neg12, rc[a0], Sc);
        A = nA; B = nB; C = nC;
    }
    float aL, aH, bL, bH;
    unpack2(accA, aL, aH); unpack2(accB, bL, bH);
    return (1.f/25.f) * (aL + aH) + (12.f/(25.f*24.f)) * (bL + bH);
}

// ---- kz3 main: 2 cols x 14 rows ----
__device__ __forceinline__ float work3(const float* __restrict__ f0, int t)
{
    const int img   = t / 567;           // 63*9
    int rem         = t - img * 567;
    const int chunk = rem / 63;
    const int cg    = rem - chunk * 63;
    const float* __restrict__ p = f0 + (size_t)img * 16384
                                + (size_t)(chunk * 14) * 128 + cg * 2;

    const u64 neg12 = pack2(-1.f, -1.f);

    u64 r0[3], rc[3];
#pragma unroll
    for (int w = 0; w < 2; w++) {
        u64 A = *reinterpret_cast<const u64*>(p);
        u64 B = *reinterpret_cast<const u64*>(p + 2);
        hstats3r(A, B, neg12, r0[w], rc[w]);
        p += 128;
    }
    u64 S0p = add2(r0[0], r0[1]);
    u64 Scp = add2(rc[0], rc[1]);

    u64 A = *reinterpret_cast<const u64*>(p);
    u64 B = *reinterpret_cast<const u64*>(p + 2);
    p += 128;

    u64 accA = 0ull, accB = 0ull;
#pragma unroll
    for (int i = 0; i < 14; i++) {
        u64 nA, nB;
        if (i < 13) {
            nA = *reinterpret_cast<const u64*>(p);
            nB = *reinterpret_cast<const u64*>(p + 2);
            p += 128;
        }
        const int sl = (i + 2) % 3, a0 = i % 3;
        hstats3r(A, B, neg12, r0[sl], rc[sl]);

        u64 S0 = add2(S0p, r0[sl]);
        u64 Sc = add2(Scp, rc[sl]);
        u64 Sr = fma2(neg12, r0[a0], r0[sl]);
        accA = fma2(S0, S0, accA);
        accB = fma2(Sr, Sr, accB);
        accB = fma2(Sc, Sc, accB);
        S0p = fma2(neg12, r0[a0], S0);
        Scp = fma2(neg12, rc[a0], Sc);
        A = nA; B = nB;
    }
    float aL, aH, bL, bH;
    unpack2(accA, aL, aH); unpack2(accB, bL, bH);
    return (1.f/9.f) * (aL + aH) + (12.f/(9.f*8.f)) * (bL + bH);
}

// ---- f^2 weighted pass, kz5: 1 block per 256x256 image ----
__device__ __forceinline__ float frow5(const float* __restrict__ f1, int img, int tid)
{
    const u64* __restrict__ q = reinterpret_cast<const u64*>(f1 + (size_t)img * 65536);
    const int x0 = 2 * (tid & 127);
    const float wx0 = (float)min(min(x0 + 1, 256 - x0), 5);
    const float wx1 = (float)min(min(x0 + 2, 255 - x0), 5);
    const u64 wx2 = pack2(wx0, wx1);

    u64 acc5 = 0ull;
#pragma unroll 8
    for (int k = 2; k < 126; k++) {
        u64 F = q[tid + (k << 8)];
        acc5 = fma2(F, mul2(F, wx2), acc5);
    }
    u64 acce = 0ull;
    const int r0 = tid >> 7;
#pragma unroll
    for (int e = 0; e < 4; e++) {
        const int k = (e < 2) ? e : (124 + e);
        const int row = r0 + 2 * k;
        const float wy = (float)min(min(row + 1, 256 - row), 5);
        u64 F = q[tid + (k << 8)];
        acce = fma2(F, mul2(F, mul2(wx2, pack2(wy, wy))), acce);
    }
    float aL, aH, eL, eH;
    unpack2(acc5, aL, aH); unpack2(acce, eL, eH);
    return 5.f * (aL + aH) + (eL + eH);
}

// ---- f^2 weighted pass, kz3: per 128x128 image ----
__device__ __forceinline__ float frow3img(const float* __restrict__ f0, int img, int tid)
{
    const u64* __restrict__ q = reinterpret_cast<const u64*>(f0 + (size_t)img * 16384);
    const int x0 = 2 * (tid & 63);
    const float wx0 = (float)min(min(x0 + 1, 128 - x0), 3);
    const float wx1 = (float)min(min(x0 + 2, 127 - x0), 3);
    const u64 wx2 = pack2(wx0, wx1);

    u64 acc3 = 0ull;
#pragma unroll 8
    for (int k = 1; k < 31; k++) {
        u64 F = q[tid + (k << 8)];
        acc3 = fma2(F, mul2(F, wx2), acc3);
    }
    u64 acce = 0ull;
    const int r0 = tid >> 6;
#pragma unroll
    for (int e = 0; e < 2; e++) {
        const int k = e * 31;
        const int row = r0 + 4 * k;
        const float wy = (float)min(min(row + 1, 128 - row), 3);
        u64 F = q[tid + (k << 8)];
        acce = fma2(F, mul2(F, mul2(wx2, pack2(wy, wy))), acce);
    }
    float aL, aH, eL, eH;
    unpack2(acc3, aL, aH); unpack2(acce, eL, eH);
    return 3.f * (aL + aH) + (eL + eH);
}

__global__ void __launch_bounds__(256, 3) fused_kernel(const float* __restrict__ f0,
                                                       const float* __restrict__ f1,
                                                       float* __restrict__ out)
{
    const int tid = threadIdx.x;
    const int b   = blockIdx.x;
    float acc = 0.f;
    double scale;

    const double sc5 = 1.0 / (32.0 * 252.0 * 252.0);
    const double sc3 = 1.0 / (32.0 * 126.0 * 126.0);

    if (b < B5F) {                                     // f^2 kz5 (positive)
        acc = frow5(f1, b, tid);
        scale = sc5;
    } else if (b < B5F + B3F) {                        // f^2 kz3 (positive), 2 imgs
        const int i0 = (b - B5F) * 2;
        acc = frow3img(f0, i0, tid) + frow3img(f0, i0 + 1, tid);
        scale = sc3;
    } else if (b < B5F + B3F + B5M) {                  // kz5 main (negative)
        acc = work5(f1, (b - B5F - B3F) * 256 + tid);
        scale = -sc5;
    } else {                                           // kz3 main (negative)
        const int t = (b - B5F - B3F - B5M) * 256 + tid;
        if (t < T3_THREADS) acc = work3(f0, t);
        scale = -sc3;
    }

#pragma unroll
    for (int o = 16; o > 0; o >>= 1) acc += __shfl_down_sync(0xffffffffu, acc, o);
    __shared__ float wsum[8];
    __shared__ bool  lastflag;
    if ((tid & 31) == 0) wsum[tid >> 5] = acc;
    __syncthreads();
    if (tid < 32) {
        float v = (tid < 8) ? wsum[tid] : 0.f;
#pragma unroll
        for (int o = 4; o > 0; o >>= 1) v += __shfl_down_sync(0xffffffffu, v, o);
        if (tid == 0) {
            g_part[b] = (double)v * scale;
            __threadfence();
            int done = atomicAdd(&g_count, 1);
            lastflag = (done == NBLOCKS - 1);
        }
    }
    __syncthreads();

    if (lastflag) {
        __threadfence();
        double s = 0.0;
        for (int i = tid; i < NBLOCKS; i += 256) s += g_part[i];
#pragma unroll
        for (int o = 16; o > 0; o >>= 1) s += __shfl_down_sync(0xffffffffu, s, o);
        __shared__ double ws[8];
        if ((tid & 31) == 0) ws[tid >> 5] = s;
        __syncthreads();
        if (tid < 32) {
            double v = (tid < 8) ? ws[tid] : 0.0;
#pragma unroll
            for (int o = 4; o > 0; o >>= 1) v += __shfl_down_sync(0xffffffffu, v, o);
            if (tid == 0) { out[0] = (float)v; g_count = 0; }
        }
    }
}

extern "C" void kernel_launch(void* const* d_in, const int* in_sizes, int n_in,
                              void* d_out, int out_size)
{
    const float* flow0 = (const float*)d_in[0];  // (32,2,128,128)
    const float* flow1 = (const float*)d_in[1];  // (32,2,256,256)
    if (n_in >= 2 && in_sizes[0] > in_sizes[1]) {
        const float* t = flow0; flow0 = flow1; flow1 = t;
    }
    fused_kernel<<<NBLOCKS, 256>>>(flow0, flow1, (float*)d_out);
}